// round 2
// baseline (speedup 1.0000x reference)
#include <cuda_runtime.h>

#define BN 2
#define CN 128
#define HN 96
#define WN 96
#define SP (HN*WN)            // 9216
#define TOT (BN*CN*SP)        // 2359296

#define EPSF 1e-8f

// Scratch (no cudaMalloc allowed)
__device__ float g_xmask[TOT];     // x * (1 + sqrt(count1))
__device__ float g_scale[BN*SP];   // per-pixel scale map (reused by both stages)

// ---------------------------------------------------------------------------
// Similarity-count stage.
//   For every pixel p: count = #{ offsets d != 0 in KxK window :
//        dot(x[:,p], x[:,p+d]) < thr * max(||x[:,p]|| * ||x[:,p+d]||, EPS) }
//   writes g_scale[p] = 1 + sqrt(count)
//
// Thread layout: block (8, 4, K). threadIdx.x = xg (4 pixels each, 32 px wide),
// threadIdx.y = row in 4-row tile, threadIdx.z = window row dy (offset split:
// partial counts summed through smem). 144 blocks cover 2x96x96 pixels.
// ---------------------------------------------------------------------------
template<int K>
__global__ void __launch_bounds__(32*K) sim_kernel(const float* __restrict__ src,
                                                   const float* __restrict__ thr_p)
{
    constexpr int H  = K/2;
    constexpr int TX = 32, TY = 4;
    constexpr int SW = 40, SH = 12;      // padded smem tile, data origin (4,4)
    constexpr int NPIX = SW*SH;          // 480
    constexpr int CH = 64;               // channels per chunk (2 chunks)
    constexpr int NT = 32*K;

    extern __shared__ float smem[];
    float* tile = smem;                  // CH*NPIX
    float* nrm  = smem + CH*NPIX;        // NPIX  (normsq, then norm in-place)
    int*   scnt = (int*)(nrm + NPIX);    // K * TY*TX partial counts

    const int xg  = threadIdx.x;         // 0..7
    const int yy  = threadIdx.y;         // 0..3
    const int dy  = threadIdx.z;         // 0..K-1
    const int tid = xg + 8*yy + 32*dy;

    const int gx0 = blockIdx.x * TX;
    const int gy0 = blockIdx.y * TY;
    const int b   = blockIdx.z;

    const float thr = *thr_p;

    for (int i = tid; i < NPIX; i += NT) nrm[i] = 0.f;

    float acc[K][4];
    #pragma unroll
    for (int dx = 0; dx < K; dx++)
        #pragma unroll
        for (int r = 0; r < 4; r++) acc[dx][r] = 0.f;

    const float* __restrict__ srcb = src + (size_t)b * CN * SP;

    // center row addr (16B aligned) and window row start (16B aligned)
    const int crow = (yy + 4) * SW + xg*4 + 4;
    const int wrow = (yy + dy + (4 - H)) * SW + xg*4;

    for (int c0 = 0; c0 < CN; c0 += CH) {
        __syncthreads();
        // ---- stage tile chunk (zero-padded halo) ----
        #pragma unroll 4
        for (int i = tid; i < CH*NPIX; i += NT) {
            int c  = i / NPIX;
            int p  = i - c*NPIX;
            int sy = p / SW;
            int sx = p - sy*SW;
            int gy = gy0 + sy - 4;
            int gx = gx0 + sx - 4;
            bool ok = ((unsigned)gy < (unsigned)HN) && ((unsigned)gx < (unsigned)WN);
            if (H < 4)   // K=5: zero the unused outer padding ring
                ok = ok && (sy >= (4-H)) && (sy < (4+TY+H)) && (sx >= (4-H)) && (sx < (4+TX+H));
            float v = 0.f;
            if (ok) v = srcb[(size_t)(c0 + c)*SP + gy*WN + gx];
            tile[i] = v;
        }
        __syncthreads();
        // ---- accumulate norm^2 per tile pixel ----
        for (int p = tid; p < NPIX; p += NT) {
            float s = 0.f;
            #pragma unroll 8
            for (int c = 0; c < CH; c++) { float v = tile[c*NPIX + p]; s = fmaf(v, v, s); }
            nrm[p] += s;
        }
        // ---- main dot-product accumulation ----
        for (int c = 0; c < CH; c++) {
            const float* tc = tile + c*NPIX;
            float4 c4 = *(const float4*)(tc + crow);
            float4 w0 = *(const float4*)(tc + wrow);
            float4 w1 = *(const float4*)(tc + wrow + 4);
            float4 w2 = *(const float4*)(tc + wrow + 8);
            float w[12] = {w0.x,w0.y,w0.z,w0.w, w1.x,w1.y,w1.z,w1.w, w2.x,w2.y,w2.z,w2.w};
            float cc[4] = {c4.x,c4.y,c4.z,c4.w};
            #pragma unroll
            for (int dx = 0; dx < K; dx++)
                #pragma unroll
                for (int r = 0; r < 4; r++)
                    acc[dx][r] = fmaf(cc[r], w[(4-H) + dx + r], acc[dx][r]);
        }
    }
    __syncthreads();
    for (int p = tid; p < NPIX; p += NT) nrm[p] = sqrtf(nrm[p]);
    __syncthreads();

    // ---- threshold & partial counts ----
    {
        float4 n4 = *(const float4*)(nrm + crow);
        float4 m0 = *(const float4*)(nrm + wrow);
        float4 m1 = *(const float4*)(nrm + wrow + 4);
        float4 m2 = *(const float4*)(nrm + wrow + 8);
        float nw[12] = {m0.x,m0.y,m0.z,m0.w, m1.x,m1.y,m1.z,m1.w, m2.x,m2.y,m2.z,m2.w};
        float nc[4]  = {n4.x,n4.y,n4.z,n4.w};
        int cnt[4] = {0,0,0,0};
        #pragma unroll
        for (int dx = 0; dx < K; dx++)
            #pragma unroll
            for (int r = 0; r < 4; r++) {
                float m  = fmaxf(nc[r]*nw[(4-H)+dx+r], EPSF);
                bool hit = acc[dx][r] < thr*m;
                bool ctr = (dy == H) && (dx == H);     // exclude the center patch
                cnt[r] += (hit && !ctr) ? 1 : 0;
            }
        #pragma unroll
        for (int r = 0; r < 4; r++)
            scnt[dy*(TY*TX) + yy*TX + xg*4 + r] = cnt[r];
    }
    __syncthreads();
    // ---- reduce over dy, write scale map ----
    for (int p = tid; p < TY*TX; p += NT) {
        int s = 0;
        #pragma unroll
        for (int d = 0; d < K; d++) s += scnt[d*(TY*TX) + p];
        int py = p >> 5;          // / TX
        int px = p & 31;          // % TX
        g_scale[b*SP + (gy0+py)*WN + (gx0+px)] = 1.f + sqrtf((float)s);
    }
}

// ---------------------------------------------------------------------------
// dst[b,c,p] = src[b,c,p] * g_scale[b,p]   (scale already includes the +1)
// ---------------------------------------------------------------------------
__global__ void apply_kernel(const float* __restrict__ src, float* __restrict__ dst)
{
    int i = blockIdx.x * blockDim.x + threadIdx.x;
    if (i >= TOT/4) return;
    int e  = i * 4;
    float4 v = ((const float4*)src)[i];
    int sp = e % SP;
    int b  = e / (CN*SP);
    float4 s = *(const float4*)(g_scale + b*SP + sp);
    v.x *= s.x; v.y *= s.y; v.z *= s.z; v.w *= s.w;
    ((float4*)dst)[i] = v;
}

extern "C" void kernel_launch(void* const* d_in, const int* in_sizes, int n_in,
                              void* d_out, int out_size)
{
    const float* x  = (const float*)d_in[0];
    const float* t1 = (const float*)d_in[1];
    const float* t2 = (const float*)d_in[2];
    float* out = (float*)d_out;

    void* xm_v = nullptr;
    cudaGetSymbolAddress(&xm_v, g_xmask);
    float* xm = (float*)xm_v;

    constexpr int SMEM = (64*480 + 480)*4 + 9*128*4;   // 129408 B
    cudaFuncSetAttribute(sim_kernel<9>, cudaFuncAttributeMaxDynamicSharedMemorySize, SMEM);
    cudaFuncSetAttribute(sim_kernel<5>, cudaFuncAttributeMaxDynamicSharedMemorySize, SMEM);

    dim3 grid(WN/32, HN/4, BN);   // (3, 24, 2) = 144 blocks

    // Stage 1: 9x9 similarity on x -> scale1
    sim_kernel<9><<<grid, dim3(8,4,9), SMEM>>>(x, t1);
    // x_mask = x * scale1
    {
        int n = TOT/4;
        apply_kernel<<<(n+255)/256, 256>>>(x, xm);
    }
    // Stage 2: 5x5 similarity on x_mask -> scale2
    sim_kernel<5><<<grid, dim3(8,4,5), SMEM>>>(xm, t2);
    // edge_map = x * scale2   (note: applied to ORIGINAL x, per reference)
    {
        int n = TOT/4;
        apply_kernel<<<(n+255)/256, 256>>>(x, out);
    }
}

// round 3
// speedup vs baseline: 1.9852x; 1.9852x over previous
#include <cuda_runtime.h>

#define BN 2
#define CN 128
#define HN 96
#define WN 96
#define SP (HN*WN)            // 9216
#define TOT (BN*CN*SP)        // 2359296

#define EPSF 1e-8f

// per-pixel scale map from stage 1 (no cudaMalloc allowed)
__device__ float g_scale[BN*SP];

__global__ void noop_kernel() {}

// ---------------------------------------------------------------------------
// Similarity-count stage with channel-split warps.
//   block (8, 4, 2K): x = 4-px group (32 px row tile), y = tile row (4),
//   z in [0,2K): dy = z%K window row, chalf = z/K channel half.
//   Each warp accumulates dots for its (dy, chalf); halves reduced via smem.
//   SCALE_IN: staged value = x * g_scale   (stage-2 input fusion)
//   EPI:      epilogue writes out = x * (1+sqrt(count))  (final apply fusion)
//   !EPI:     writes g_scale = 1+sqrt(count)
// ---------------------------------------------------------------------------
template<int K, bool SCALE_IN, bool EPI>
__global__ void __launch_bounds__(64*K) sim_kernel(const float* __restrict__ src,
                                                   const float* __restrict__ thr_p,
                                                   float* __restrict__ outp)
{
    constexpr int H  = K/2;
    constexpr int TX = 32, TY = 4;
    constexpr int SW = 40, SH = 12;      // padded smem tile, data origin (4,4)
    constexpr int NPIX = SW*SH;          // 480
    constexpr int CH = 64;               // channels per chunk (2 chunks)
    constexpr int NT = 64*K;             // threads
    constexpr int SLOT = K*4 + 1;        // padded reduction slot (floats)

    extern __shared__ float smem[];
    float* tile = smem;                  // CH*NPIX  (reused as redbuf at end)
    float* nrm  = smem + CH*NPIX;        // NPIX
    int*   scnt = (int*)(nrm + NPIX);    // K * 128 partial counts

    const int xg    = threadIdx.x;       // 0..7
    const int yy    = threadIdx.y;       // 0..3
    const int z     = threadIdx.z;       // 0..2K-1
    const int chalf = (z >= K) ? 1 : 0;
    const int dy    = z - chalf*K;
    const int tid   = xg + 8*yy + 32*z;

    const int gx0 = blockIdx.x * TX;
    const int gy0 = blockIdx.y * TY;
    const int b   = blockIdx.z;

    const float thr = *thr_p;
    const float* __restrict__ srcb = src + (size_t)b * CN * SP;

    // ---- per-thread staging positions (≤2), fully precomputed ----
    int   posA[2]; int goffA[2]; float svalA[2]; bool okA[2];
    int npos = 0;
    #pragma unroll
    for (int j = 0; j < 2; j++) {
        int pos = tid + j*NT;
        if (pos < NPIX) {
            int sy = pos / SW;
            int sx = pos - sy*SW;
            int gy = gy0 + sy - 4;
            int gx = gx0 + sx - 4;
            bool ok = ((unsigned)gy < (unsigned)HN) && ((unsigned)gx < (unsigned)WN);
            if (H < 4)   // K=5: zero unused outer padding ring
                ok = ok && (sy >= (4-H)) && (sy < (4+TY+H)) && (sx >= (4-H)) && (sx < (4+TX+H));
            int goff = ok ? (gy*WN + gx) : 0;
            float sv = 1.f;
            if (SCALE_IN && ok) sv = g_scale[b*SP + goff];
            posA[npos] = pos; goffA[npos] = goff; svalA[npos] = sv; okA[npos] = ok;
            npos++;
            nrm[pos] = 0.f;
        }
    }

    float acc[K][4];
    #pragma unroll
    for (int dx = 0; dx < K; dx++)
        #pragma unroll
        for (int r = 0; r < 4; r++) acc[dx][r] = 0.f;

    const int crow = (yy + 4) * SW + xg*4 + 4;           // 16B aligned
    const int wrow = (yy + dy + (4 - H)) * SW + xg*4;    // 16B aligned

    for (int c0 = 0; c0 < CN; c0 += CH) {
        __syncthreads();
        // ---- stage chunk: channel-strided, no div/mod in loop ----
        for (int j = 0; j < npos; j++) {
            const int   pos  = posA[j];
            const float sv   = svalA[j];
            const bool  ok   = okA[j];
            const float* gp  = srcb + (size_t)c0*SP + goffA[j];
            float* tp = tile + pos;
            #pragma unroll 4
            for (int c = 0; c < CH; c++) {
                float v = 0.f;
                if (ok) v = gp[c*SP];
                if (SCALE_IN) v *= sv;
                tp[c*NPIX] = v;
            }
        }
        __syncthreads();
        // ---- norm^2 accumulation (per-thread own pixels) ----
        for (int j = 0; j < npos; j++) {
            const float* tp = tile + posA[j];
            float s = 0.f;
            #pragma unroll 8
            for (int c = 0; c < CH; c++) { float v = tp[c*NPIX]; s = fmaf(v, v, s); }
            nrm[posA[j]] += s;
        }
        // ---- dot accumulation: this warp's channel half of the chunk ----
        {
            const float* tc0 = tile + (chalf*(CH/2))*NPIX;
            #pragma unroll 2
            for (int c = 0; c < CH/2; c++) {
                const float* tc = tc0 + c*NPIX;
                float4 c4 = *(const float4*)(tc + crow);
                float4 w0 = *(const float4*)(tc + wrow);
                float4 w1 = *(const float4*)(tc + wrow + 4);
                float4 w2 = *(const float4*)(tc + wrow + 8);
                float w[12] = {w0.x,w0.y,w0.z,w0.w, w1.x,w1.y,w1.z,w1.w, w2.x,w2.y,w2.z,w2.w};
                float cc[4] = {c4.x,c4.y,c4.z,c4.w};
                #pragma unroll
                for (int dx = 0; dx < K; dx++)
                    #pragma unroll
                    for (int r = 0; r < 4; r++)
                        acc[dx][r] = fmaf(cc[r], w[(4-H) + dx + r], acc[dx][r]);
            }
        }
    }
    __syncthreads();   // tile reads done; nrm writes done

    // finalize norms; chalf=1 publishes partial dots into (reused) tile smem
    for (int j = 0; j < npos; j++) nrm[posA[j]] = sqrtf(nrm[posA[j]]);
    {
        const int slot = (dy*4 + yy)*8 + xg;
        if (chalf == 1) {
            float* rb = tile + slot*SLOT;
            #pragma unroll
            for (int dx = 0; dx < K; dx++)
                #pragma unroll
                for (int r = 0; r < 4; r++) rb[dx*4 + r] = acc[dx][r];
        }
        __syncthreads();
        if (chalf == 0) {
            const float* rb = tile + slot*SLOT;
            #pragma unroll
            for (int dx = 0; dx < K; dx++)
                #pragma unroll
                for (int r = 0; r < 4; r++) acc[dx][r] += rb[dx*4 + r];

            // ---- threshold & partial counts ----
            float4 n4 = *(const float4*)(nrm + crow);
            float4 m0 = *(const float4*)(nrm + wrow);
            float4 m1 = *(const float4*)(nrm + wrow + 4);
            float4 m2 = *(const float4*)(nrm + wrow + 8);
            float nw[12] = {m0.x,m0.y,m0.z,m0.w, m1.x,m1.y,m1.z,m1.w, m2.x,m2.y,m2.z,m2.w};
            float nc[4]  = {n4.x,n4.y,n4.z,n4.w};
            int cnt[4] = {0,0,0,0};
            #pragma unroll
            for (int dx = 0; dx < K; dx++)
                #pragma unroll
                for (int r = 0; r < 4; r++) {
                    float m  = fmaxf(nc[r]*nw[(4-H)+dx+r], EPSF);
                    bool hit = acc[dx][r] < thr*m;
                    bool ctr = (dy == H) && (dx == H);
                    cnt[r] += (hit && !ctr) ? 1 : 0;
                }
            #pragma unroll
            for (int r = 0; r < 4; r++)
                scnt[dy*128 + yy*TX + xg*4 + r] = cnt[r];
        }
    }
    __syncthreads();

    // ---- reduce over dy -> per-pixel scale ----
    if (tid < 128) {
        int s = 0;
        #pragma unroll
        for (int d = 0; d < K; d++) s += scnt[d*128 + tid];
        float sc = 1.f + sqrtf((float)s);
        if (EPI) {
            nrm[tid] = sc;     // local scale for fused epilogue
        } else {
            int py = tid >> 5, px = tid & 31;
            g_scale[b*SP + (gy0+py)*WN + (gx0+px)] = sc;
        }
    }

    if (EPI) {
        __syncthreads();
        // out[c, tile px] = x[c, tile px] * scale2   (x re-read from L2)
        float* __restrict__ ob = outp + (size_t)b * CN * SP;
        #pragma unroll 4
        for (int i = tid; i < CN*128; i += NT) {
            int c  = i >> 7;
            int px = i & 127;
            int y  = px >> 5, xx = px & 31;
            int off = c*SP + (gy0+y)*WN + (gx0+xx);
            ob[off] = srcb[off] * nrm[px];
        }
    }
}

extern "C" void kernel_launch(void* const* d_in, const int* in_sizes, int n_in,
                              void* d_out, int out_size)
{
    const float* x  = (const float*)d_in[0];
    const float* t1 = (const float*)d_in[1];
    const float* t2 = (const float*)d_in[2];
    float* out = (float*)d_out;

    constexpr int SMEM9 = (64*480 + 480)*4 + 9*128*4;   // 129408 B
    constexpr int SMEM5 = (64*480 + 480)*4 + 5*128*4;   // 127360 B
    cudaFuncSetAttribute((const void*)sim_kernel<9,false,false>,
                         cudaFuncAttributeMaxDynamicSharedMemorySize, SMEM9);
    cudaFuncSetAttribute((const void*)sim_kernel<5,true,true>,
                         cudaFuncAttributeMaxDynamicSharedMemorySize, SMEM5);

    dim3 grid(WN/32, HN/4, BN);   // (3, 24, 2) = 144 blocks

    // launch order [noop, sim9, sim5, noop] puts global launch idx 5 == sim9
    // (ncu capture is -s 5 -c 1) so the dominant kernel gets profiled.
    noop_kernel<<<1, 1>>>();
    // Stage 1: 9x9 similarity on x -> g_scale
    sim_kernel<9,false,false><<<grid, dim3(8,4,18), SMEM9>>>(x, t1, nullptr);
    // Stage 2: 5x5 similarity on (x*scale1) with fused final apply -> out
    sim_kernel<5,true,true><<<grid, dim3(8,4,10), SMEM5>>>(x, t2, out);
    noop_kernel<<<1, 1>>>();
}